// round 10
// baseline (speedup 1.0000x reference)
#include <cuda_runtime.h>

// Multi-SM fused ContrastiveLoss, one launch, grid=64, ONE inter-block sync.
// R10: the per-(subject,warp) counts array is TRANSPOSED and widened to u32
// (wc[warp*NSUBJ + subject]) to kill the 16-way smem bank conflicts of the
// R3..R9 layout (wc[s*32+w] u16: lanes l, l+2 were exactly 32 banks apart in
// the per-subject prefix scan -> ~16k crossbar cycles/block ~= 11us).
// A2's scan now reads consecutive words per lane: conflict-free.

#define NSUBJ 1024
#define NWARP 32
#define MAXP 50
#define CAP 51
#define GRID 64
#define T 1024
#define NLOSS 4

#define WCNT_B (NWARP * NSUBJ * 4)       // 131072 (u32, [warp][subject])
#define SMEM_TOTAL (WCNT_B + 4096 /*scnt*/ + 2*MAXP*4*2 + 16 + 128 + 64)

__device__ volatile unsigned g_flagA[GRID];   // count+scatter published
__device__ volatile unsigned g_flagL[NLOSS];  // loss partial published
__device__ float g_part[NLOSS];               // per-loss-block partials
__device__ unsigned short g_bcnt16[GRID * NSUBJ];         // [block][subject]
__device__ unsigned short g_lidx[GRID * NSUBJ * CAP];     // [block][subject][slot] local idx

// subject_ids may be int64 or (jax x64-off) int32: one broadcast load + vote.
__device__ __forceinline__ bool detect64(const void* p, int lane) {
    long long v = ((const long long*)p)[lane & 15];
    bool ok = (v >= 0 && v < (long long)NSUBJ);
    return __all_sync(0xFFFFFFFFu, ok);
}

__device__ __forceinline__ long long sid_or_neg(const void* p, int i, int B, bool is64) {
    if (i >= B) return -1ll;
    return is64 ? ((const long long*)p)[i] : (long long)((const int*)p)[i];
}

// Warp-cooperative: map (subject, global slot) -> global element index.
__device__ __forceinline__ int resolve_idx(int s, int slot, int lane, int eT) {
    int u0 = (int)g_bcnt16[lane * NSUBJ + s];
    int u1 = (int)g_bcnt16[(lane + 32) * NSUBJ + s];
    int s0 = u0, s1 = u1;
#pragma unroll
    for (int d = 1; d < 32; d <<= 1) {
        int t0 = __shfl_up_sync(0xFFFFFFFFu, s0, d);
        int t1 = __shfl_up_sync(0xFFFFFFFFu, s1, d);
        if (lane >= d) { s0 += t0; s1 += t1; }
    }
    int tot0 = __shfl_sync(0xFFFFFFFFu, s0, 31);
    int e0 = s0 - u0;                 // exclusive offset of block `lane`
    int e1 = tot0 + s1 - u1;          // exclusive offset of block `lane+32`
    int blk = -1, loc = 0;
    if (slot >= e0 && slot < e0 + u0) { blk = lane;      loc = slot - e0; }
    if (slot >= e1 && slot < e1 + u1) { blk = lane + 32; loc = slot - e1; }
    int idx = 0;
    if (blk >= 0)
        idx = blk * eT + (int)g_lidx[(blk * NSUBJ + s) * CAP + loc];
    unsigned m = __ballot_sync(0xFFFFFFFFu, blk >= 0);
    return __shfl_sync(0xFFFFFFFFu, idx, __ffs(m) - 1);
}

__global__ void __launch_bounds__(T, 1)
fused_contrastive(const void* __restrict__ sids, const float* __restrict__ x,
                  float* __restrict__ out, int B, int D) {
    extern __shared__ unsigned char sm[];
    unsigned* wc = (unsigned*)sm;                          // [warp*NSUBJ + s] u32
    int* scnt = (int*)(sm + WCNT_B);                       // [s] totals (loss blocks)
    int* ii   = scnt + NSUBJ;                              // encoded s*CAP+slot
    int* jj   = ii + 2 * MAXP;
    int* npn  = jj + 2 * MAXP;
    float* part = (float*)(npn + 4);                       // [32]

    const int tid = threadIdx.x, lane = tid & 31, w = tid >> 5;
    const int b = blockIdx.x;
    const bool is64 = detect64(sids, lane);
    const unsigned epoch = g_flagA[b] + 1u;                // own flag: replay-safe

    const int e = (B + GRID * T - 1) / (GRID * T);         // 1 for B=65536
    const int eT = e * T;
    const int base = b * eT + w * e * 32;

    // zero wc (consecutive words per thread stride: conflict-free)
    for (int k = tid; k < NWARP * NSUBJ; k += T) wc[k] = 0u;
    __syncthreads();

    // ---- A1: per-(subject,warp) counts; retain k=0 sid in a register ----
    long long v0 = -1ll;
    for (int k = 0; k < e; k++) {
        long long v = sid_or_neg(sids, base + k * 32 + lane, B, is64);
        if (k == 0) v0 = v;
        bool valid = v >= 0;
        int s = valid ? (int)v : 0;
        int key = valid ? s : (NSUBJ + lane);
        unsigned mask = __match_any_sync(0xFFFFFFFFu, key);
        if (valid && lane == (__ffs(mask) - 1))
            wc[w * NSUBJ + s] += __popc(mask);
    }
    __syncthreads();

    // ---- A2: block-local exclusive prefix over warps (conflict-free scan) ----
    {
        int s = tid;
        int run = 0;
#pragma unroll
        for (int c = 0; c < NWARP; c++) {
            int v = (int)wc[c * NSUBJ + s];
            wc[c * NSUBJ + s] = (unsigned)run;
            run += v;
        }
        g_bcnt16[b * NSUBJ + s] = (unsigned short)run;     // coalesced u16
    }
    __syncthreads();

    // ---- A3: block-LOCAL order-preserving scatter (no cross-block offset) ----
    for (int k = 0; k < e; k++) {
        int i = base + k * 32 + lane;
        long long v = (k == 0) ? v0 : sid_or_neg(sids, i, B, is64);
        bool valid = v >= 0;
        int s = valid ? (int)v : 0;
        int key = valid ? s : (NSUBJ + lane);
        unsigned mask = __match_any_sync(0xFFFFFFFFu, key);
        if (valid) {
            int rank = __popc(mask & ((1u << lane) - 1u));
            int cur = (int)wc[w * NSUBJ + s];              // all lanes read before leader store
            int slot = cur + rank;                         // LOCAL slot
            if (lane == (__ffs(mask) - 1))
                wc[w * NSUBJ + s] = (unsigned)(cur + __popc(mask));
            if (slot < CAP)
                g_lidx[(b * NSUBJ + s) * CAP + slot] = (unsigned short)(i - b * eT);
        }
    }
    __syncthreads();

    // ---- publish; non-loss blocks exit (single sync point) ----
    if (tid == 0) {
        __threadfence();
        g_flagA[b] = epoch;
    }
    if (b >= NLOSS) return;

    // ---- wait for all blocks (parallel flag poll) ----
    for (int t = tid; t < GRID; t += T)
        while (g_flagA[t] < epoch) { }
    __syncthreads();
    __threadfence();

    // ---- B: per-subject totals (thread s sums its 64-block column) ----
    {
        int s = tid;
        int tot = 0;
#pragma unroll 16
        for (int c = 0; c < GRID; c++) tot += (int)g_bcnt16[c * NSUBJ + s];
        scnt[s] = tot;
    }
    __syncthreads();

    // ---- D1: reference pair enumeration (pos: thread 0, neg: thread 32;
    //      independent given scnt). Handles are s*CAP + global_slot. ----
    if (tid == 0) {                                        // positive pairs
        int npos = 0;
        for (int s = 0; s < NSUBJ && npos < MAXP; s++) {
            int cs = scnt[s];
            if (cs < 2) continue;
            int til = cs < CAP ? cs : CAP;
            for (int a = 0; a < til && npos < MAXP; a++)
                for (int bb = a + 1; bb < til && npos < MAXP; bb++) {
                    ii[npos] = s * CAP + a;
                    jj[npos] = s * CAP + bb;
                    npos++;
                }
        }
        npn[0] = npos;
    }
    if (tid == 32) {                                       // negative pairs
        int nneg = 0;
        for (int s = 0; s < NSUBJ && nneg < MAXP; s++) {
            int cs = scnt[s];
            if (cs == 0) continue;
            int til = cs < CAP ? cs : CAP;
            for (int o = 0; o < NSUBJ; o++) {
                int co = scnt[o];
                if (co == 0) continue;
                if (o == s) continue;                      // python: continue precedes break
                if (nneg >= MAXP) break;
                int tjl = co < CAP ? co : CAP;
                for (int a = 0; a < til && nneg < MAXP; a++)
                    for (int bb = 0; bb < tjl && nneg < MAXP; bb++) {
                        ii[MAXP + nneg] = s * CAP + a;
                        jj[MAXP + nneg] = o * CAP + bb;
                        nneg++;
                    }
            }
        }
        npn[1] = nneg;
    }
    __syncthreads();

    // ---- D2: warp per pair (p % NLOSS == b); lazy slot resolution + loss ----
    const int npos = npn[0], nneg = npn[1], n = npos + nneg;
    float acc = 0.0f;
    const int nvec = D / 4;                                // D=384 -> 96 float4
    for (int p = b + NLOSS * w; p < n; p += NLOSS * NWARP) {
        int slot = (p < npos) ? p : (MAXP + (p - npos));
        int hi = ii[slot], hj = jj[slot];
        int i = resolve_idx(hi / CAP, hi % CAP, lane, eT);
        int j = resolve_idx(hj / CAP, hj % CAP, lane, eT);
        const float4* xi = (const float4*)(x + (long long)i * D);
        const float4* xj = (const float4*)(x + (long long)j * D);
        float sxx = 0.f, syy = 0.f, sxy = 0.f;
        for (int q = lane; q < nvec; q += 32) {
            float4 a = xi[q];
            float4 bq = xj[q];
            sxx += a.x * a.x + a.y * a.y + a.z * a.z + a.w * a.w;
            syy += bq.x * bq.x + bq.y * bq.y + bq.z * bq.z + bq.w * bq.w;
            sxy += a.x * bq.x + a.y * bq.y + a.z * bq.z + a.w * bq.w;
        }
#pragma unroll
        for (int o = 16; o; o >>= 1) {
            sxx += __shfl_xor_sync(0xFFFFFFFFu, sxx, o);
            syy += __shfl_xor_sync(0xFFFFFFFFu, syy, o);
            sxy += __shfl_xor_sync(0xFFFFFFFFu, sxy, o);
        }
        float ni = fmaxf(sqrtf(sxx), 1e-12f);
        float nj = fmaxf(sqrtf(syy), 1e-12f);
        float sc = (sxy / (ni * nj)) * 2.0f;               // / TEMPERATURE (0.5)
        float xs = (p < npos) ? -sc : sc;
        acc += fmaxf(xs, 0.f) + log1pf(expf(-fabsf(xs))); // softplus(xs)
    }

    // acc replicated across lanes -> lane 0's copy IS the warp partial
    if (lane == 0) part[w] = acc;
    __syncthreads();
    if (w == 0) {
        float v = part[lane];
#pragma unroll
        for (int o = 16; o; o >>= 1) v += __shfl_xor_sync(0xFFFFFFFFu, v, o);
        if (lane == 0) {
            g_part[b] = v;
            __threadfence();
            g_flagL[b] = epoch;
        }
    }

    // ---- block 0 combines the NLOSS partials deterministically ----
    if (b == 0) {
        if (tid < NLOSS)
            while (g_flagL[tid] < epoch) { }
        __syncthreads();
        __threadfence();
        if (tid == 0) {
            float tot = 0.0f;
#pragma unroll
            for (int r = 0; r < NLOSS; r++) tot += g_part[r];
            out[0] = tot / (float)n;
        }
    }
}

extern "C" void kernel_launch(void* const* d_in, const int* in_sizes, int n_in,
                              void* d_out, int out_size) {
    const float* x = (const float*)d_in[0];   // identity_tokens [B, D] fp32
    const void* sids = d_in[1];               // subject_ids [B]
    int B = in_sizes[1];
    int D = in_sizes[0] / B;

    cudaFuncSetAttribute(fused_contrastive,
                         cudaFuncAttributeMaxDynamicSharedMemorySize, SMEM_TOTAL);

    fused_contrastive<<<GRID, T, SMEM_TOTAL>>>(sids, x, (float*)d_out, B, D);
}